// round 13
// baseline (speedup 1.0000x reference)
#include <cuda_runtime.h>
#include <cuda_bf16.h>

#define S        8192
#define TPB      512
#define CHUNKS   (S / TPB)           // 16 chunks of 512 positions
#define NWARP    (TPB / 32)          // 16 warps
#define NW       (S / 32)            // 256 mask words per row
#define SECT     4
#define CPS      (CHUNKS / SECT)     // 4 chunks per section (64 words)
#define MAXROWS  2048

__device__ float    g_partial[MAXROWS];
__device__ float    g_count[MAXROWS];
__device__ unsigned g_done;          // zero-init; self-resets every pass

__global__ __launch_bounds__(TPB, 4)
void prox_loss_kernel(const float4* __restrict__ logits,
                      const int*    __restrict__ labels,
                      const float*  __restrict__ cw,
                      float*        __restrict__ out,
                      int nrows) {
    // M[0]=true2, M[1]=true3, M[2]=pred2, M[3]=pred3 (padded +1 both ends)
    __shared__ unsigned M[4][NW + 2];
    __shared__ float    ce_s[S];                 // 32 KB
    __shared__ float    lut[2048];               // f1 by 11-bit true-window
    __shared__ float    cw_s[4];
    __shared__ float    ws0[NWARP], ws1[NWARP], ws2[NWARP], ws3[NWARP];
    __shared__ bool     s_is_last;

    const int row  = blockIdx.x;
    const int tid  = threadIdx.x;
    const int lane = tid & 31;
    const int warp = tid >> 5;

    const float NEG_LOG2_08 = -0.321928095f;     // log2(0.8)

    // ---- LUT + pad + cw init ----
    #pragma unroll
    for (int v = tid; v < 2048; v += TPB) {
        float f = 1.0f;
        if (!((v >> 5) & 1)) {                   // no true switch AT the position
            const unsigned fold = (__brev((unsigned)v & 31u) >> 27)
                                | (((unsigned)v >> 6) & 31u);  // bit(k-1)=dist k
            if (fold) f = exp2f((float)__ffs(fold) * NEG_LOG2_08);
        }
        lut[v] = f;
    }
    if (tid < 4) { M[tid][0] = 0u; M[tid][NW + 1] = 0u; cw_s[tid] = __ldg(&cw[tid]); }
    __syncthreads();

    const float4* lg = logits + (size_t)row * S;
    const int*    lb = labels + (size_t)row * S;

    int   cntI  = 0;
    bool  hasp2 = false, hasp3 = false;
    float base  = 0.0f, C2 = 0.0f, C3 = 0.0f;

    // Phase-1 consume: softmax CE -> smem, pred bools, ballots -> masks.
    auto p1_consume = [&](int p, float4 l, int y) {
        const bool gwz = l.w > l.z;
        const bool p3b = (l.w > l.x) & (l.w > l.y) & gwz;
        const bool p2b = (l.z > l.x) & (l.z > l.y) & !gwz;

        // softmax without max-subtraction (logits ~ N(0,1): safe in fp32)
        const float esum = __expf(l.x) + __expf(l.y) + __expf(l.z) + __expf(l.w);
        const float lse  = __logf(esum);

        const int ys = (y < 0) ? 0 : y;
        const float lya = (ys & 1) ? l.y : l.x;
        const float lyb = (ys & 1) ? l.w : l.z;
        const float ly  = (ys & 2) ? lyb : lya;
        ce_s[p] = (y < 0) ? 0.0f : cw_s[ys] * (lse - ly);
        cntI += (y >= 0);

        const bool t3b = (y == 3);
        const unsigned bt2 = __ballot_sync(0xFFFFFFFFu, y == 2);
        const unsigned bt3 = __ballot_sync(0xFFFFFFFFu, t3b);
        const unsigned bp2 = __ballot_sync(0xFFFFFFFFu, p2b);
        const unsigned bp3 = __ballot_sync(0xFFFFFFFFu, p3b);
        hasp2 |= (bp2 != 0u);
        hasp3 |= (bp3 != 0u);
        if (lane == 0) {
            const int wi = (p >> 5) + 1;
            M[0][wi] = bt2; M[1][wi] = bt3; M[2][wi] = bp2; M[3][wi] = bp3;
        }
    };

    // Phase-2 per-position: windows + LUT; tfac deferred via base/C2/C3.
    auto p2_pos = [&](int pl) {
        const int wi = (pl >> 5) + 1;
        const unsigned t2c = M[0][wi], t3c = M[1][wi];
        const unsigned p2c = M[2][wi], p3c = M[3][wi];

        const unsigned y3 = (t3c >> lane) & 1u;
        const unsigned a3 = (p3c >> lane) & 1u;
        const unsigned tm = ((t2c | t3c) >> lane) & 1u;
        const unsigned pm = ((p2c | p3c) >> lane) & 1u;

        const int bpp = pl + 27;
        const int wi0 = bpp >> 5;
        const int sh  = bpp & 31;

        const unsigned tw = __funnelshift_r(M[a3][wi0], M[a3][wi0 + 1], sh) & 0x7FFu;
        const unsigned pw = __funnelshift_r(M[2 + y3][wi0], M[2 + y3][wi0 + 1], sh) & 0x7FFu;

        const float f1 = pm ? lut[tw] : 1.0f;
        const float t  = ce_s[pl] * f1;
        // tfac assuming any_pred=true; correction restores exact 2.0 later
        // (any=false => pw==0 => f2a=1.5; +0.5*t gives exactly 2.0*t).
        const float f2a = tm ? (pw ? 1.0f : 1.5f) : 1.0f;
        base += t * f2a;
        const float corr = tm ? t * (2.0f - f2a) : 0.0f;
        C2 += y3 ? 0.0f : corr;
        C3 += y3 ? corr : 0.0f;
    };

    // ---- Stage 0: phase 1 on section 0 ----
    #pragma unroll
    for (int c = 0; c < CPS; c++) {
        const int p = c * TPB + tid;
        const float4 l = __ldcs(&lg[p]);
        const int    y = __ldcs(&lb[p]);
        p1_consume(p, l, y);
    }
    __syncthreads();

    // ---- Stages 1..3: phase1(section s) overlapped with phase2(section s-1).
    //      Loads issued first; independent phase-2 ALU covers their latency.
    //      Last word of section s-1 (word 64s-1) deferred (needs section s). ----
    #pragma unroll
    for (int s = 1; s < SECT; s++) {
        const int skipw = 64 * s - 1;
        #pragma unroll 2
        for (int j = 0; j < CPS; j++) {
            const int cN = s * CPS + j;
            const int pN = cN * TPB + tid;
            const float4 l = __ldcs(&lg[pN]);
            const int    y = __ldcs(&lb[pN]);

            const int pC = (cN - CPS) * TPB + tid;
            if ((pC >> 5) != skipw)              // warp-uniform predicate
                p2_pos(pC);

            p1_consume(pN, l, y);
        }
        __syncthreads();
    }

    // ---- Final: phase2 on section 3 + the 3 deferred boundary words ----
    #pragma unroll 2
    for (int c = CHUNKS - CPS; c < CHUNKS; c++)
        p2_pos(c * TPB + tid);
    if (warp < 3)
        p2_pos((64 * (warp + 1) - 1) * 32 + lane);

    const int any2 = __syncthreads_or(hasp2 ? 1 : 0);
    const int any3 = __syncthreads_or(hasp3 ? 1 : 0);

    // ---- Block reduction of (base, C2, C3, cnt) ----
    float cnt = (float)cntI;
    #pragma unroll
    for (int o = 16; o > 0; o >>= 1) {
        base += __shfl_down_sync(0xFFFFFFFFu, base, o);
        C2   += __shfl_down_sync(0xFFFFFFFFu, C2,   o);
        C3   += __shfl_down_sync(0xFFFFFFFFu, C3,   o);
        cnt  += __shfl_down_sync(0xFFFFFFFFu, cnt,  o);
    }
    if (lane == 0) { ws0[warp] = base; ws1[warp] = C2; ws2[warp] = C3; ws3[warp] = cnt; }
    __syncthreads();
    if (warp == 0) {
        base = (lane < NWARP) ? ws0[lane] : 0.0f;
        C2   = (lane < NWARP) ? ws1[lane] : 0.0f;
        C3   = (lane < NWARP) ? ws2[lane] : 0.0f;
        cnt  = (lane < NWARP) ? ws3[lane] : 0.0f;
        #pragma unroll
        for (int o = 8; o > 0; o >>= 1) {
            base += __shfl_down_sync(0xFFFFFFFFu, base, o);
            C2   += __shfl_down_sync(0xFFFFFFFFu, C2,   o);
            C3   += __shfl_down_sync(0xFFFFFFFFu, C3,   o);
            cnt  += __shfl_down_sync(0xFFFFFFFFu, cnt,  o);
        }
        if (lane == 0) {
            const float rowsum = base + (any2 ? 0.0f : C2) + (any3 ? 0.0f : C3);
            g_partial[row] = rowsum;
            g_count[row]   = cnt;
            __threadfence();
            const unsigned prev = atomicAdd(&g_done, 1u);
            s_is_last = (prev == (unsigned)(nrows - 1));
        }
    }
    __syncthreads();

    // ---- Last block: global reduce + divide, reset counter ----
    if (s_is_last) {
        float s = 0.0f, c = 0.0f;
        for (int i = tid; i < nrows; i += TPB) {
            s += *((volatile float*)&g_partial[i]);
            c += *((volatile float*)&g_count[i]);
        }
        #pragma unroll
        for (int o = 16; o > 0; o >>= 1) {
            s += __shfl_down_sync(0xFFFFFFFFu, s, o);
            c += __shfl_down_sync(0xFFFFFFFFu, c, o);
        }
        if (lane == 0) { ws0[warp] = s; ws1[warp] = c; }
        __syncthreads();
        if (warp == 0) {
            s = (lane < NWARP) ? ws0[lane] : 0.0f;
            c = (lane < NWARP) ? ws1[lane] : 0.0f;
            #pragma unroll
            for (int o = 8; o > 0; o >>= 1) {
                s += __shfl_down_sync(0xFFFFFFFFu, s, o);
                c += __shfl_down_sync(0xFFFFFFFFu, c, o);
            }
            if (lane == 0) {
                out[0] = s / fmaxf(c, 1.0f);
                g_done = 0u;
            }
        }
    }
}

extern "C" void kernel_launch(void* const* d_in, const int* in_sizes, int n_in,
                              void* d_out, int out_size) {
    const float4* logits = (const float4*)d_in[0];
    const int*    labels = (const int*)d_in[1];
    const float*  cw     = (const float*)d_in[2];
    float*        out    = (float*)d_out;

    const int nrows = in_sizes[1] / S;   // B = 512

    prox_loss_kernel<<<nrows, TPB>>>(logits, labels, cw, out, nrows);
}

// round 14
// speedup vs baseline: 1.0707x; 1.0707x over previous
#include <cuda_runtime.h>
#include <cuda_bf16.h>

#define S        8192
#define TPB      1024
#define CHUNKS   (S / TPB)          // 8 positions per thread
#define NWARP    (TPB / 32)         // 32 warps
#define NW       (S / 32)           // 256 mask words per row
#define MAXROWS  2048

__device__ float    g_partial[MAXROWS];
__device__ float    g_count[MAXROWS];
__device__ unsigned g_done;          // zero-init; self-resets every pass

__global__ __launch_bounds__(TPB, 2)
void prox_loss_kernel(const float4* __restrict__ logits,
                      const int*    __restrict__ labels,
                      const float*  __restrict__ cw,
                      float*        __restrict__ out,
                      int nrows) {
    // M[0]=true2, M[1]=true3, M[2]=pred2, M[3]=pred3 (padded +1 both ends)
    __shared__ unsigned M[4][NW + 2];
    __shared__ float    ce_s[S];                 // 32 KB
    __shared__ float    lut[2048];               // f1 by 11-bit true-window
    __shared__ float    cw_s[4];
    __shared__ float    ws_sum[NWARP], ws_cnt[NWARP];
    __shared__ bool     s_is_last;

    const int row  = blockIdx.x;
    const int tid  = threadIdx.x;
    const int lane = tid & 31;
    const int warp = tid >> 5;

    const float NEG_LOG2_08 = -0.321928095f;     // log2(0.8)

    // ---- LUT + pad + cw init (before the mask barrier) ----
    #pragma unroll
    for (int v = tid; v < 2048; v += TPB) {
        float f = 1.0f;
        if (!((v >> 5) & 1)) {                   // no true switch AT the position
            const unsigned fold = (__brev((unsigned)v & 31u) >> 27)
                                | (((unsigned)v >> 6) & 31u);  // bit(k-1)=dist k
            if (fold) f = exp2f((float)__ffs(fold) * NEG_LOG2_08);
        }
        lut[v] = f;
    }
    if (tid < 4) { M[tid][0] = 0u; M[tid][NW + 1] = 0u; cw_s[tid] = __ldg(&cw[tid]); }
    __syncthreads();

    const float4* lg = logits + (size_t)row * S;
    const int*    lb = labels + (size_t)row * S;

    float cnt = 0.0f;
    bool  hasp2 = false, hasp3 = false;

    // ---- Phase 1: load (streaming), CE -> smem, pred bools, ballots -> smem ----
    #pragma unroll 4
    for (int c = 0; c < CHUNKS; c++) {
        const int p = c * TPB + tid;
        const float4 l = __ldcs(&lg[p]);
        const int    y = __ldcs(&lb[p]);

        // first-occurrence argmax membership for classes 2/3 only
        const bool gwz = l.w > l.z;
        const bool p3b = (l.w > l.x) & (l.w > l.y) & gwz;
        const bool p2b = (l.z > l.x) & (l.z > l.y) & !gwz;

        // softmax without max-subtraction (logits ~ N(0,1): no overflow risk)
        const float esum = __expf(l.x) + __expf(l.y) + __expf(l.z) + __expf(l.w);
        const float lse  = __logf(esum);

        const int ys = (y < 0) ? 0 : y;
        const float lya = (ys & 1) ? l.y : l.x;
        const float lyb = (ys & 1) ? l.w : l.z;
        const float ly  = (ys & 2) ? lyb : lya;
        ce_s[p] = (y < 0) ? 0.0f : cw_s[ys] * (lse - ly);

        const bool t3b = (y == 3);
        const unsigned bt2 = __ballot_sync(0xFFFFFFFFu, y == 2);
        const unsigned bt3 = __ballot_sync(0xFFFFFFFFu, t3b);
        const unsigned bp2 = __ballot_sync(0xFFFFFFFFu, p2b);
        const unsigned bp3 = __ballot_sync(0xFFFFFFFFu, p3b);
        const unsigned bv  = __ballot_sync(0xFFFFFFFFu, y >= 0);
        hasp2 |= (bp2 != 0u);
        hasp3 |= (bp3 != 0u);
        if (lane == 0) {
            const int wi = (p >> 5) + 1;
            M[0][wi] = bt2; M[1][wi] = bt3; M[2][wi] = bp2; M[3][wi] = bp3;
            cnt += (float)__popc(bv);
        }
    }

    const int any2 = __syncthreads_or(hasp2 ? 1 : 0);
    const int any3 = __syncthreads_or(hasp3 ? 1 : 0);

    float sum = 0.0f;

    // ---- Phase 2: lean per-position factor via windows + LUT ----
    #pragma unroll 4
    for (int c = 0; c < CHUNKS; c++) {
        const int p  = c * TPB + tid;
        const int wi = (p >> 5) + 1;             // warp-uniform padded word

        const unsigned t2c = M[0][wi], t3c = M[1][wi];
        const unsigned p2c = M[2][wi], p3c = M[3][wi];

        const unsigned y3 = (t3c >> lane) & 1u;
        const unsigned a3 = (p3c >> lane) & 1u;
        const unsigned tm = ((t2c | t3c) >> lane) & 1u;
        const unsigned pm = ((p2c | p3c) >> lane) & 1u;

        // 11-bit windows, start bit = p+27 in padded bitspace
        const int bpp = p + 27;
        const int wi0 = bpp >> 5;
        const int sh  = bpp & 31;

        // true-mask window of the PREDICTED class -> decay via LUT
        const unsigned tw = __funnelshift_r(M[a3][wi0], M[a3][wi0 + 1], sh) & 0x7FFu;
        // pred-mask window of the LABEL class (incl. center) -> tfac
        const unsigned pw = __funnelshift_r(M[2 + y3][wi0], M[2 + y3][wi0 + 1], sh) & 0x7FFu;

        const float f1 = pm ? lut[tw] : 1.0f;
        const int  anyc = y3 ? any3 : any2;
        const float f2 = tm ? (anyc ? (pw ? 1.0f : 1.5f) : 2.0f) : 1.0f;

        sum += ce_s[p] * (f1 * f2);
    }

    // ---- Block reduction ----
    #pragma unroll
    for (int o = 16; o > 0; o >>= 1) {
        sum += __shfl_down_sync(0xFFFFFFFFu, sum, o);
        cnt += __shfl_down_sync(0xFFFFFFFFu, cnt, o);
    }
    if (lane == 0) { ws_sum[warp] = sum; ws_cnt[warp] = cnt; }
    __syncthreads();
    if (warp == 0) {
        sum = ws_sum[lane];
        cnt = ws_cnt[lane];
        #pragma unroll
        for (int o = 16; o > 0; o >>= 1) {
            sum += __shfl_down_sync(0xFFFFFFFFu, sum, o);
            cnt += __shfl_down_sync(0xFFFFFFFFu, cnt, o);
        }
        if (lane == 0) {
            g_partial[row] = sum;
            g_count[row]   = cnt;
            __threadfence();
            const unsigned prev = atomicAdd(&g_done, 1u);
            s_is_last = (prev == (unsigned)(nrows - 1));
        }
    }
    __syncthreads();

    // ---- Last block: global reduce + divide, reset counter ----
    if (s_is_last) {
        float s = 0.0f, c = 0.0f;
        for (int i = tid; i < nrows; i += TPB) {
            s += *((volatile float*)&g_partial[i]);
            c += *((volatile float*)&g_count[i]);
        }
        #pragma unroll
        for (int o = 16; o > 0; o >>= 1) {
            s += __shfl_down_sync(0xFFFFFFFFu, s, o);
            c += __shfl_down_sync(0xFFFFFFFFu, c, o);
        }
        if (lane == 0) { ws_sum[warp] = s; ws_cnt[warp] = c; }
        __syncthreads();
        if (warp == 0) {
            s = ws_sum[lane];
            c = ws_cnt[lane];
            #pragma unroll
            for (int o = 16; o > 0; o >>= 1) {
                s += __shfl_down_sync(0xFFFFFFFFu, s, o);
                c += __shfl_down_sync(0xFFFFFFFFu, c, o);
            }
            if (lane == 0) {
                out[0] = s / fmaxf(c, 1.0f);
                g_done = 0u;
            }
        }
    }
}

extern "C" void kernel_launch(void* const* d_in, const int* in_sizes, int n_in,
                              void* d_out, int out_size) {
    const float4* logits = (const float4*)d_in[0];
    const int*    labels = (const int*)d_in[1];
    const float*  cw     = (const float*)d_in[2];
    float*        out    = (float*)d_out;

    const int nrows = in_sizes[1] / S;   // B = 512

    prox_loss_kernel<<<nrows, TPB>>>(logits, labels, cw, out, nrows);
}

// round 15
// speedup vs baseline: 1.1509x; 1.0749x over previous
#include <cuda_runtime.h>
#include <cuda_bf16.h>

#define S        8192
#define TPB      512
#define CHUNKS   (S / TPB)          // 16 positions per thread
#define NWARP    (TPB / 32)         // 16 warps
#define NW       (S / 32)           // 256 mask words per row
#define MAXROWS  2048

__device__ float    g_partial[MAXROWS];
__device__ float    g_count[MAXROWS];
__device__ unsigned g_done;          // zero-init; self-resets every pass

__global__ __launch_bounds__(TPB, 4)
void prox_loss_kernel(const float4* __restrict__ logits,
                      const int*    __restrict__ labels,
                      const float*  __restrict__ cw,
                      float*        __restrict__ out,
                      int nrows) {
    // Interleaved masks: Mq[wi] = (true2, true3, pred2, pred3), padded both ends.
    __shared__ uint4    Mq[NW + 2];
    __shared__ float    ce_s[S];                 // 32 KB
    __shared__ float    lut[2048];               // f1 by 11-bit true-window
    __shared__ float    cw_s[4];
    __shared__ float    ws_sum[NWARP], ws_cnt[NWARP];
    __shared__ bool     s_is_last;

    const int row  = blockIdx.x;
    const int tid  = threadIdx.x;
    const int lane = tid & 31;
    const int warp = tid >> 5;

    const float NEG_LOG2_08 = -0.321928095f;     // log2(0.8)

    // ---- LUT + pad + cw init (before the mask barrier) ----
    #pragma unroll
    for (int v = tid; v < 2048; v += TPB) {
        float f = 1.0f;
        if (!((v >> 5) & 1)) {                   // no true switch AT the position
            const unsigned fold = (__brev((unsigned)v & 31u) >> 27)
                                | (((unsigned)v >> 6) & 31u);  // bit(k-1)=dist k
            if (fold) f = exp2f((float)__ffs(fold) * NEG_LOG2_08);
        }
        lut[v] = f;
    }
    if (tid < 2)  Mq[tid * (NW + 1)] = make_uint4(0u, 0u, 0u, 0u);
    if (tid < 4)  cw_s[tid] = __ldg(&cw[tid]);
    __syncthreads();

    const float4* lg = logits + (size_t)row * S;
    const int*    lb = labels + (size_t)row * S;

    float cnt = 0.0f;
    bool  hasp2 = false, hasp3 = false;

    // ---- Phase 1: load (streaming), CE -> smem, pred bools, ballots -> smem ----
    #pragma unroll 4
    for (int c = 0; c < CHUNKS; c++) {
        const int p = c * TPB + tid;
        const float4 l = __ldcs(&lg[p]);
        const int    y = __ldcs(&lb[p]);

        // first-occurrence argmax membership for classes 2/3 only
        const bool gwz = l.w > l.z;
        const bool p3b = (l.w > l.x) & (l.w > l.y) & gwz;
        const bool p2b = (l.z > l.x) & (l.z > l.y) & !gwz;

        // softmax without max-subtraction (logits ~ N(0,1): no overflow risk)
        const float esum = __expf(l.x) + __expf(l.y) + __expf(l.z) + __expf(l.w);
        const float lse  = __logf(esum);

        const int ys = (y < 0) ? 0 : y;
        const float lya = (ys & 1) ? l.y : l.x;
        const float lyb = (ys & 1) ? l.w : l.z;
        const float ly  = (ys & 2) ? lyb : lya;
        ce_s[p] = (y < 0) ? 0.0f : cw_s[ys] * (lse - ly);

        const bool t3b = (y == 3);
        const unsigned bt2 = __ballot_sync(0xFFFFFFFFu, y == 2);
        const unsigned bt3 = __ballot_sync(0xFFFFFFFFu, t3b);
        const unsigned bp2 = __ballot_sync(0xFFFFFFFFu, p2b);
        const unsigned bp3 = __ballot_sync(0xFFFFFFFFu, p3b);
        const unsigned bv  = __ballot_sync(0xFFFFFFFFu, y >= 0);
        hasp2 |= (bp2 != 0u);
        hasp3 |= (bp3 != 0u);
        if (lane == 0) {
            Mq[(p >> 5) + 1] = make_uint4(bt2, bt3, bp2, bp3);
            cnt += (float)__popc(bv);
        }
    }

    const int any2 = __syncthreads_or(hasp2 ? 1 : 0);
    const int any3 = __syncthreads_or(hasp3 ? 1 : 0);

    float sum = 0.0f;
    const bool lo5 = (lane < 5);
    const int  sh  = (lane + 27) & 31;

    // ---- Phase 2: two LDS.128 per position cover center + both windows ----
    #pragma unroll 4
    for (int c = 0; c < CHUNKS; c++) {
        const int p   = c * TPB + tid;
        const int wi0 = (p + 27) >> 5;           // in {wi-1, wi}; wi = (p>>5)+1

        const uint4 V0 = Mq[wi0];
        const uint4 V1 = Mq[wi0 + 1];

        // center words (word wi): V1 for lanes<5, V0 otherwise
        const unsigned ct2 = lo5 ? V1.x : V0.x;
        const unsigned ct3 = lo5 ? V1.y : V0.y;
        const unsigned cp2 = lo5 ? V1.z : V0.z;
        const unsigned cp3 = lo5 ? V1.w : V0.w;

        const unsigned y3 = (ct3 >> lane) & 1u;
        const unsigned a3 = (cp3 >> lane) & 1u;
        const unsigned tm = ((ct2 | ct3) >> lane) & 1u;
        const unsigned pm = ((cp2 | cp3) >> lane) & 1u;

        // 11-bit windows from register components, funnel shift
        const unsigned Ta = a3 ? V0.y : V0.x;
        const unsigned Tb = a3 ? V1.y : V1.x;
        const unsigned Pa = y3 ? V0.w : V0.z;
        const unsigned Pb = y3 ? V1.w : V1.z;
        const unsigned tw = __funnelshift_r(Ta, Tb, sh) & 0x7FFu;
        const unsigned pw = __funnelshift_r(Pa, Pb, sh) & 0x7FFu;

        const float f1 = pm ? lut[tw] : 1.0f;
        const int  anyc = y3 ? any3 : any2;
        const float f2 = tm ? (anyc ? (pw ? 1.0f : 1.5f) : 2.0f) : 1.0f;

        sum += ce_s[p] * (f1 * f2);
    }

    // ---- Block reduction ----
    #pragma unroll
    for (int o = 16; o > 0; o >>= 1) {
        sum += __shfl_down_sync(0xFFFFFFFFu, sum, o);
        cnt += __shfl_down_sync(0xFFFFFFFFu, cnt, o);
    }
    if (lane == 0) { ws_sum[warp] = sum; ws_cnt[warp] = cnt; }
    __syncthreads();
    if (warp == 0) {
        sum = (lane < NWARP) ? ws_sum[lane] : 0.0f;
        cnt = (lane < NWARP) ? ws_cnt[lane] : 0.0f;
        #pragma unroll
        for (int o = 8; o > 0; o >>= 1) {
            sum += __shfl_down_sync(0xFFFFFFFFu, sum, o);
            cnt += __shfl_down_sync(0xFFFFFFFFu, cnt, o);
        }
        if (lane == 0) {
            g_partial[row] = sum;
            g_count[row]   = cnt;
            __threadfence();
            const unsigned prev = atomicAdd(&g_done, 1u);
            s_is_last = (prev == (unsigned)(nrows - 1));
        }
    }
    __syncthreads();

    // ---- Last block: global reduce + divide, reset counter ----
    if (s_is_last) {
        float s = 0.0f, c = 0.0f;
        for (int i = tid; i < nrows; i += TPB) {
            s += *((volatile float*)&g_partial[i]);
            c += *((volatile float*)&g_count[i]);
        }
        #pragma unroll
        for (int o = 16; o > 0; o >>= 1) {
            s += __shfl_down_sync(0xFFFFFFFFu, s, o);
            c += __shfl_down_sync(0xFFFFFFFFu, c, o);
        }
        if (lane == 0) { ws_sum[warp] = s; ws_cnt[warp] = c; }
        __syncthreads();
        if (warp == 0) {
            s = (lane < NWARP) ? ws_sum[lane] : 0.0f;
            c = (lane < NWARP) ? ws_cnt[lane] : 0.0f;
            #pragma unroll
            for (int o = 8; o > 0; o >>= 1) {
                s += __shfl_down_sync(0xFFFFFFFFu, s, o);
                c += __shfl_down_sync(0xFFFFFFFFu, c, o);
            }
            if (lane == 0) {
                out[0] = s / fmaxf(c, 1.0f);
                g_done = 0u;
            }
        }
    }
}

extern "C" void kernel_launch(void* const* d_in, const int* in_sizes, int n_in,
                              void* d_out, int out_size) {
    const float4* logits = (const float4*)d_in[0];
    const int*    labels = (const int*)d_in[1];
    const float*  cw     = (const float*)d_in[2];
    float*        out    = (float*)d_out;

    const int nrows = in_sizes[1] / S;   // B = 512

    prox_loss_kernel<<<nrows, TPB>>>(logits, labels, cw, out, nrows);
}

// round 16
// speedup vs baseline: 1.1604x; 1.0083x over previous
#include <cuda_runtime.h>
#include <cuda_bf16.h>

#define S        8192
#define TPB      512
#define CHUNKS   (S / TPB)          // 16 positions per thread (phase 1)
#define PAIRS    (S / (2 * TPB))    // 8 pair-iterations (phase 2)
#define NWARP    (TPB / 32)         // 16 warps
#define NW       (S / 32)           // 256 mask words per row
#define MAXROWS  2048

__device__ float    g_partial[MAXROWS];
__device__ float    g_count[MAXROWS];
__device__ unsigned g_done;          // zero-init; self-resets every pass

__global__ __launch_bounds__(TPB, 4)
void prox_loss_kernel(const float4* __restrict__ logits,
                      const int*    __restrict__ labels,
                      const float*  __restrict__ cw,
                      float*        __restrict__ out,
                      int nrows) {
    // Interleaved masks: Mq[wi] = (true2, true3, pred2, pred3), padded both ends.
    __shared__ uint4    Mq[NW + 2];
    __shared__ float    ce_s[S];                 // 32 KB
    __shared__ float    lut[2048];               // f1 by 11-bit true-window
    __shared__ float    cw_s[4];
    __shared__ float    ws_sum[NWARP], ws_cnt[NWARP];
    __shared__ bool     s_is_last;

    const int row  = blockIdx.x;
    const int tid  = threadIdx.x;
    const int lane = tid & 31;
    const int warp = tid >> 5;

    const float NEG_LOG2_08 = -0.321928095f;     // log2(0.8)

    // ---- LUT + pad + cw init (before the mask barrier) ----
    #pragma unroll
    for (int v = tid; v < 2048; v += TPB) {
        float f = 1.0f;
        if (!((v >> 5) & 1)) {                   // no true switch AT the position
            const unsigned fold = (__brev((unsigned)v & 31u) >> 27)
                                | (((unsigned)v >> 6) & 31u);  // bit(k-1)=dist k
            if (fold) f = exp2f((float)__ffs(fold) * NEG_LOG2_08);
        }
        lut[v] = f;
    }
    if (tid < 2)  Mq[tid * (NW + 1)] = make_uint4(0u, 0u, 0u, 0u);
    if (tid < 4)  cw_s[tid] = __ldg(&cw[tid]);
    __syncthreads();

    const float4* lg = logits + (size_t)row * S;
    const int*    lb = labels + (size_t)row * S;

    float cnt = 0.0f;
    bool  hasp2 = false, hasp3 = false;

    // ---- Phase 1: load (streaming), CE -> smem, pred bools, ballots -> smem ----
    #pragma unroll 4
    for (int c = 0; c < CHUNKS; c++) {
        const int p = c * TPB + tid;
        const float4 l = __ldcs(&lg[p]);
        const int    y = __ldcs(&lb[p]);

        // first-occurrence argmax membership for classes 2/3 only
        const bool gwz = l.w > l.z;
        const bool p3b = (l.w > l.x) & (l.w > l.y) & gwz;
        const bool p2b = (l.z > l.x) & (l.z > l.y) & !gwz;

        // softmax without max-subtraction (logits ~ N(0,1): no overflow risk)
        const float esum = __expf(l.x) + __expf(l.y) + __expf(l.z) + __expf(l.w);
        const float lse  = __logf(esum);

        const int ys = (y < 0) ? 0 : y;
        const float lya = (ys & 1) ? l.y : l.x;
        const float lyb = (ys & 1) ? l.w : l.z;
        const float ly  = (ys & 2) ? lyb : lya;
        ce_s[p] = (y < 0) ? 0.0f : cw_s[ys] * (lse - ly);

        const bool t3b = (y == 3);
        const unsigned bt2 = __ballot_sync(0xFFFFFFFFu, y == 2);
        const unsigned bt3 = __ballot_sync(0xFFFFFFFFu, t3b);
        const unsigned bp2 = __ballot_sync(0xFFFFFFFFu, p2b);
        const unsigned bp3 = __ballot_sync(0xFFFFFFFFu, p3b);
        const unsigned bv  = __ballot_sync(0xFFFFFFFFu, y >= 0);
        hasp2 |= (bp2 != 0u);
        hasp3 |= (bp3 != 0u);
        if (lane == 0) {
            Mq[(p >> 5) + 1] = make_uint4(bt2, bt3, bp2, bp3);
            cnt += (float)__popc(bv);
        }
    }

    const int any2 = __syncthreads_or(hasp2 ? 1 : 0);
    const int any3 = __syncthreads_or(hasp3 ? 1 : 0);

    float sum = 0.0f;

    // ---- Phase 2: each thread handles an adjacent pair (p, p+1).
    //      One funnel per mask serves both positions:
    //        window(p)   = res & 0x7FF
    //        window(p+1) = (res >> 1) & 0x7FF
    //      Centers come free: bit 5 (pos0) / bit 6 (pos1). ----
    #pragma unroll 4
    for (int c = 0; c < PAIRS; c++) {
        const int idx = c * TPB + tid;           // 0..4095
        const int p   = idx << 1;                // even position
        const int q   = p + 27;                  // padded bitspace start
        const int wi0 = q >> 5;
        const int sh  = q & 31;

        const uint4 V0 = Mq[wi0];
        const uint4 V1 = Mq[wi0 + 1];

        const unsigned wt2 = __funnelshift_r(V0.x, V1.x, sh);  // bits q..q+31
        const unsigned wt3 = __funnelshift_r(V0.y, V1.y, sh);
        const unsigned wp2 = __funnelshift_r(V0.z, V1.z, sh);
        const unsigned wp3 = __funnelshift_r(V0.w, V1.w, sh);

        const unsigned wtm = wt2 | wt3;
        const unsigned wpm = wp2 | wp3;

        const float2 ce2 = *reinterpret_cast<const float2*>(&ce_s[p]);

        // ---- position p (window bits 0..10, center bit 5) ----
        {
            const unsigned y3 = (wt3 >> 5) & 1u;
            const unsigned a3 = (wp3 >> 5) & 1u;
            const unsigned tm = (wtm >> 5) & 1u;
            const unsigned pm = (wpm >> 5) & 1u;

            const unsigned tw = (a3 ? wt3 : wt2) & 0x7FFu;
            const unsigned pw = (y3 ? wp3 : wp2) & 0x7FFu;

            const float f1 = pm ? lut[tw] : 1.0f;
            const int  anyc = y3 ? any3 : any2;
            const float f2 = tm ? (anyc ? (pw ? 1.0f : 1.5f) : 2.0f) : 1.0f;
            sum += ce2.x * (f1 * f2);
        }

        // ---- position p+1 (window bits 1..11, center bit 6) ----
        {
            const unsigned y3 = (wt3 >> 6) & 1u;
            const unsigned a3 = (wp3 >> 6) & 1u;
            const unsigned tm = (wtm >> 6) & 1u;
            const unsigned pm = (wpm >> 6) & 1u;

            const unsigned tw = ((a3 ? wt3 : wt2) >> 1) & 0x7FFu;
            const unsigned pw = ((y3 ? wp3 : wp2) >> 1) & 0x7FFu;

            const float f1 = pm ? lut[tw] : 1.0f;
            const int  anyc = y3 ? any3 : any2;
            const float f2 = tm ? (anyc ? (pw ? 1.0f : 1.5f) : 2.0f) : 1.0f;
            sum += ce2.y * (f1 * f2);
        }
    }

    // ---- Block reduction ----
    #pragma unroll
    for (int o = 16; o > 0; o >>= 1) {
        sum += __shfl_down_sync(0xFFFFFFFFu, sum, o);
        cnt += __shfl_down_sync(0xFFFFFFFFu, cnt, o);
    }
    if (lane == 0) { ws_sum[warp] = sum; ws_cnt[warp] = cnt; }
    __syncthreads();
    if (warp == 0) {
        sum = (lane < NWARP) ? ws_sum[lane] : 0.0f;
        cnt = (lane < NWARP) ? ws_cnt[lane] : 0.0f;
        #pragma unroll
        for (int o = 8; o > 0; o >>= 1) {
            sum += __shfl_down_sync(0xFFFFFFFFu, sum, o);
            cnt += __shfl_down_sync(0xFFFFFFFFu, cnt, o);
        }
        if (lane == 0) {
            g_partial[row] = sum;
            g_count[row]   = cnt;
            __threadfence();
            const unsigned prev = atomicAdd(&g_done, 1u);
            s_is_last = (prev == (unsigned)(nrows - 1));
        }
    }
    __syncthreads();

    // ---- Last block: global reduce + divide, reset counter ----
    if (s_is_last) {
        float s = 0.0f, c = 0.0f;
        for (int i = tid; i < nrows; i += TPB) {
            s += *((volatile float*)&g_partial[i]);
            c += *((volatile float*)&g_count[i]);
        }
        #pragma unroll
        for (int o = 16; o > 0; o >>= 1) {
            s += __shfl_down_sync(0xFFFFFFFFu, s, o);
            c += __shfl_down_sync(0xFFFFFFFFu, c, o);
        }
        if (lane == 0) { ws_sum[warp] = s; ws_cnt[warp] = c; }
        __syncthreads();
        if (warp == 0) {
            s = (lane < NWARP) ? ws_sum[lane] : 0.0f;
            c = (lane < NWARP) ? ws_cnt[lane] : 0.0f;
            #pragma unroll
            for (int o = 8; o > 0; o >>= 1) {
                s += __shfl_down_sync(0xFFFFFFFFu, s, o);
                c += __shfl_down_sync(0xFFFFFFFFu, c, o);
            }
            if (lane == 0) {
                out[0] = s / fmaxf(c, 1.0f);
                g_done = 0u;
            }
        }
    }
}

extern "C" void kernel_launch(void* const* d_in, const int* in_sizes, int n_in,
                              void* d_out, int out_size) {
    const float4* logits = (const float4*)d_in[0];
    const int*    labels = (const int*)d_in[1];
    const float*  cw     = (const float*)d_in[2];
    float*        out    = (float*)d_out;

    const int nrows = in_sizes[1] / S;   // B = 512

    prox_loss_kernel<<<nrows, TPB>>>(logits, labels, cw, out, nrows);
}